// round 15
// baseline (speedup 1.0000x reference)
#include <cuda_runtime.h>
#include <cuda_bf16.h>
#include <cstdint>

// MultiDense via mma.sync: per i, D[j=32, l=128] = x @ W^T + bias, split-bf16
// 3-pass (AhBh + AhBl + AlBh), fp32 accum. One CTA (128 thr) per i, 3 CTAs/SM.
// R15: split-k pipelined W staging — k<64 staged up front, k>=64 staged in
// micro-batches interleaved with ks0-3 MMAs. x preloaded to regs (R13-style).

#define I_DIM 8192
#define J_DIM 32
#define IN_F  128
#define OUT_F 128
#define NODE_MASK 4095
#define PROW_SRC 129
#define W_SRC_FLOATS (OUT_F * PROW_SRC)     // 16512

#define RSTRIDE 136                          // bf16 row stride (272B): ldmatrix conflict-free
#define OFF_WHI 0                            // 128 x 136 bf16 = 34816
#define OFF_WLO 34816
#define OFF_BIAS 69632                       // 128 f32
#define SMEM_BYTES 70144                     // 3 CTAs/SM

__device__ __forceinline__ uint32_t smem_u32(const void* p) {
    uint32_t a;
    asm("{ .reg .u64 t; cvta.to.shared.u64 t, %1; cvt.u32.u64 %0, t; }" : "=r"(a) : "l"(p));
    return a;
}

__device__ __forceinline__ void ldmx4(uint32_t* r, uint32_t addr) {
    asm volatile("ldmatrix.sync.aligned.m8n8.x4.shared.b16 {%0,%1,%2,%3}, [%4];"
                 : "=r"(r[0]), "=r"(r[1]), "=r"(r[2]), "=r"(r[3]) : "r"(addr));
}

__device__ __forceinline__ void mma_bf16(float* c, uint32_t a0, uint32_t a1, uint32_t a2,
                                         uint32_t a3, uint32_t b0, uint32_t b1) {
    asm volatile(
        "mma.sync.aligned.m16n8k16.row.col.f32.bf16.bf16.f32 "
        "{%0,%1,%2,%3}, {%4,%5,%6,%7}, {%8,%9}, {%0,%1,%2,%3};"
        : "+f"(c[0]), "+f"(c[1]), "+f"(c[2]), "+f"(c[3])
        : "r"(a0), "r"(a1), "r"(a2), "r"(a3), "r"(b0), "r"(b1));
}

__device__ __forceinline__ uint32_t cvt_hi(float2 v) {
    __nv_bfloat162 h;
    h.x = __float2bfloat16(v.x);
    h.y = __float2bfloat16(v.y);
    return *reinterpret_cast<uint32_t*>(&h);
}
__device__ __forceinline__ uint32_t cvt_lo(float2 v, uint32_t hi) {
    __nv_bfloat162 h = *reinterpret_cast<__nv_bfloat162*>(&hi);
    __nv_bfloat162 l;
    l.x = __float2bfloat16(v.x - __bfloat162float(h.x));
    l.y = __float2bfloat16(v.y - __bfloat162float(h.y));
    return *reinterpret_cast<uint32_t*>(&l);
}

__global__ __launch_bounds__(128, 3)
void multidense_kernel(const float* __restrict__ x_in,
                       const int* __restrict__ inds,
                       const float* __restrict__ params,
                       float* __restrict__ out)
{
    extern __shared__ char smem[];
    const uint32_t sb = smem_u32(smem);
    float* bias_s = reinterpret_cast<float*>(smem + OFF_BIAS);

    const int i = blockIdx.x;
    const int t = threadIdx.x;            // 0..127
    const int node = inds[i] & NODE_MASK;

    const int wid = t >> 5, lane = t & 31;
    const int j0 = (wid >> 1) * 16;
    const int l0 = (wid & 1) * 64;
    const int g = lane >> 2, tg = lane & 3;

    // ---- x preload + convert to A fragments (R13-proven) ----
    uint32_t ahi[32], alo[32];            // [row01*16 + m]: m = k-octet
    {
        const float* xg = x_in + (size_t)i * (J_DIM * IN_F);
        const float* r0p = xg + (j0 + g) * IN_F + 2 * tg;
        const float* r1p = xg + (j0 + 8 + g) * IN_F + 2 * tg;
        #pragma unroll
        for (int m = 0; m < 16; m++) {
            float2 u0 = *reinterpret_cast<const float2*>(r0p + 8 * m);
            float2 u1 = *reinterpret_cast<const float2*>(r1p + 8 * m);
            ahi[m]      = cvt_hi(u0);  alo[m]      = cvt_lo(u0, ahi[m]);
            ahi[16 + m] = cvt_hi(u1);  alo[16 + m] = cvt_lo(u1, ahi[16 + m]);
        }
    }

    const float* pg = params + (size_t)node * W_SRC_FLOATS;

    // ---- phase A: stage W k<64 (16 quads/thread, 2 batches of 8, STS.64) ----
    // quad idx: l = idx>>4, k = (idx&15)*4  (16 quads per row-half)
    #pragma unroll
    for (int qb = 0; qb < 2; qb++) {
        float v[8][4]; int lv[8], kv[8];
        #pragma unroll
        for (int m = 0; m < 8; m++) {
            int idx = t + 128 * (qb * 8 + m);           // 0..2047
            lv[m] = idx >> 4;
            kv[m] = (idx & 15) * 4;
            const float* s = pg + lv[m] * PROW_SRC + kv[m];
            v[m][0] = s[0]; v[m][1] = s[1]; v[m][2] = s[2]; v[m][3] = s[3];
        }
        #pragma unroll
        for (int m = 0; m < 8; m++) {
            float2 p0 = make_float2(v[m][0], v[m][1]);
            float2 p1 = make_float2(v[m][2], v[m][3]);
            uint32_t h0 = cvt_hi(p0), h1 = cvt_hi(p1);
            uint32_t q0 = cvt_lo(p0, h0), q1 = cvt_lo(p1, h1);
            uint32_t o = (uint32_t)(lv[m] * RSTRIDE + kv[m]) * 2;   // 8B-aligned
            *reinterpret_cast<uint2*>(smem + OFF_WHI + o) = make_uint2(h0, h1);
            *reinterpret_cast<uint2*>(smem + OFF_WLO + o) = make_uint2(q0, q1);
        }
    }
    bias_s[t] = pg[t * PROW_SRC + IN_F];

    __syncthreads();                       // W k<64 + bias ready

    // ---- accumulators + B smem pointers ----
    float c[8][4];
    #pragma unroll
    for (int nt = 0; nt < 8; nt++)
        #pragma unroll
        for (int q = 0; q < 4; q++) c[nt][q] = 0.0f;

    const int brow  = l0 + (lane & 7) + (lane >> 4) * 8;
    const int bkoff = ((lane >> 3) & 1) * 8;
    const uint32_t b_hi = sb + OFF_WHI + (uint32_t)(brow * RSTRIDE + bkoff) * 2;
    const uint32_t b_lo = sb + OFF_WLO + (uint32_t)(brow * RSTRIDE + bkoff) * 2;
    const uint32_t PSTEP = 16 * RSTRIDE * 2;

#define DO_KS(ks)                                                                       \
    {                                                                                   \
        const uint32_t ko = (uint32_t)(ks) * 32;                                        \
        uint32_t bh[4][4], bl[4][4];                                                    \
        _Pragma("unroll")                                                               \
        for (int p = 0; p < 4; p++) {                                                   \
            ldmx4(bh[p], b_hi + p * PSTEP + ko);                                        \
            ldmx4(bl[p], b_lo + p * PSTEP + ko);                                        \
        }                                                                               \
        const uint32_t ah0 = ahi[2*(ks)],   ah1 = ahi[16+2*(ks)];                       \
        const uint32_t ah2 = ahi[2*(ks)+1], ah3 = ahi[16+2*(ks)+1];                     \
        const uint32_t al0 = alo[2*(ks)],   al1 = alo[16+2*(ks)];                       \
        const uint32_t al2 = alo[2*(ks)+1], al3 = alo[16+2*(ks)+1];                     \
        _Pragma("unroll")                                                               \
        for (int nt = 0; nt < 8; nt++) {                                                \
            const int p = nt >> 1, q = (nt & 1) * 2;                                    \
            mma_bf16(c[nt], ah0, ah1, ah2, ah3, bh[p][q], bh[p][q + 1]);                \
            mma_bf16(c[nt], ah0, ah1, ah2, ah3, bl[p][q], bl[p][q + 1]);                \
            mma_bf16(c[nt], al0, al1, al2, al3, bh[p][q], bh[p][q + 1]);                \
        }                                                                               \
    }

// phase-B micro-batch: load 4 quads of W k>=64 into regs (bt = 0..3)
#define STAGE_B_LDG(bt)                                                                 \
    {                                                                                   \
        _Pragma("unroll")                                                               \
        for (int m = 0; m < 4; m++) {                                                   \
            int idx = t + 128 * ((bt) * 4 + m);        /* 0..2047 */                    \
            lvb[m] = idx >> 4;                                                          \
            kvb[m] = (idx & 15) * 4 + 64;                                               \
            const float* s = pg + lvb[m] * PROW_SRC + kvb[m];                           \
            vb[m][0] = s[0]; vb[m][1] = s[1]; vb[m][2] = s[2]; vb[m][3] = s[3];         \
        }                                                                               \
    }
#define STAGE_B_STS()                                                                   \
    {                                                                                   \
        _Pragma("unroll")                                                               \
        for (int m = 0; m < 4; m++) {                                                   \
            float2 p0 = make_float2(vb[m][0], vb[m][1]);                                \
            float2 p1 = make_float2(vb[m][2], vb[m][3]);                                \
            uint32_t h0 = cvt_hi(p0), h1 = cvt_hi(p1);                                  \
            uint32_t q0 = cvt_lo(p0, h0), q1 = cvt_lo(p1, h1);                          \
            uint32_t o = (uint32_t)(lvb[m] * RSTRIDE + kvb[m]) * 2;                     \
            *reinterpret_cast<uint2*>(smem + OFF_WHI + o) = make_uint2(h0, h1);         \
            *reinterpret_cast<uint2*>(smem + OFF_WLO + o) = make_uint2(q0, q1);         \
        }                                                                               \
    }

    // ---- phase B: stage W k>=64 interleaved with ks0-3 compute ----
    float vb[4][4]; int lvb[4], kvb[4];
    STAGE_B_LDG(0);
    DO_KS(0);
    STAGE_B_STS();
    STAGE_B_LDG(1);
    DO_KS(1);
    STAGE_B_STS();
    STAGE_B_LDG(2);
    DO_KS(2);
    STAGE_B_STS();
    STAGE_B_LDG(3);
    DO_KS(3);
    STAGE_B_STS();

    __syncthreads();                       // W k>=64 ready

    DO_KS(4);
    DO_KS(5);
    DO_KS(6);
    DO_KS(7);

#undef DO_KS
#undef STAGE_B_LDG
#undef STAGE_B_STS

    // ---- epilogue (verified): c0,c1 -> row j0+g; c2,c3 -> row j0+g+8 ----
    float* og = out + (size_t)i * (J_DIM * OUT_F);
    #pragma unroll
    for (int nt = 0; nt < 8; nt++) {
        const int l = l0 + nt * 8 + 2 * tg;
        const float2 b2 = *reinterpret_cast<const float2*>(bias_s + l);
        float2 r0; r0.x = c[nt][0] + b2.x; r0.y = c[nt][1] + b2.y;
        float2 r1; r1.x = c[nt][2] + b2.x; r1.y = c[nt][3] + b2.y;
        *reinterpret_cast<float2*>(og + (j0 + g)     * OUT_F + l) = r0;
        *reinterpret_cast<float2*>(og + (j0 + g + 8) * OUT_F + l) = r1;
    }
}

extern "C" void kernel_launch(void* const* d_in, const int* in_sizes, int n_in,
                              void* d_out, int out_size)
{
    const float* x_in   = (const float*)d_in[0];
    const int*   inds   = (const int*)d_in[1];
    const float* params = (const float*)d_in[2];
    float*       out    = (float*)d_out;

    static bool attr_set = false;
    if (!attr_set) {
        cudaFuncSetAttribute(multidense_kernel,
                             cudaFuncAttributeMaxDynamicSharedMemorySize, SMEM_BYTES);
        attr_set = true;
    }

    multidense_kernel<<<I_DIM, 128, SMEM_BYTES>>>(x_in, inds, params, out);
}

// round 16
// speedup vs baseline: 1.1636x; 1.1636x over previous
#include <cuda_runtime.h>
#include <cuda_bf16.h>
#include <cstdint>

// MultiDense via mma.sync: per i, D[j=32, l=128] = x @ W^T + bias, split-bf16
// 3-pass (AhBh + AhBl + AlBh), fp32 accum. One CTA (128 thr) per i, 3 CTAs/SM.
// R16 = R13 + x routed through a coalesced smem bounce buffer (aliased over
// the WHI plane; zero extra smem) to cut x-load L1 wavefronts ~8x.

#define I_DIM 8192
#define J_DIM 32
#define IN_F  128
#define OUT_F 128
#define NODE_MASK 4095
#define PROW_SRC 129
#define W_SRC_FLOATS (OUT_F * PROW_SRC)     // 16512

#define RSTRIDE 136                          // W bf16 row stride: ldmatrix conflict-free
#define XSTRIDE 132                          // x fp32 row stride (16B-aligned rows, bank-spread)
#define OFF_WHI 0                            // 128 x 136 bf16 = 34816  (x buffer aliases [0,16896))
#define OFF_WLO 34816
#define OFF_BIAS 69632                       // 128 f32
#define SMEM_BYTES 70144                     // 3 CTAs/SM

__device__ __forceinline__ uint32_t smem_u32(const void* p) {
    uint32_t a;
    asm("{ .reg .u64 t; cvta.to.shared.u64 t, %1; cvt.u32.u64 %0, t; }" : "=r"(a) : "l"(p));
    return a;
}

__device__ __forceinline__ void ldmx4(uint32_t* r, uint32_t addr) {
    asm volatile("ldmatrix.sync.aligned.m8n8.x4.shared.b16 {%0,%1,%2,%3}, [%4];"
                 : "=r"(r[0]), "=r"(r[1]), "=r"(r[2]), "=r"(r[3]) : "r"(addr));
}

__device__ __forceinline__ void mma_bf16(float* c, uint32_t a0, uint32_t a1, uint32_t a2,
                                         uint32_t a3, uint32_t b0, uint32_t b1) {
    asm volatile(
        "mma.sync.aligned.m16n8k16.row.col.f32.bf16.bf16.f32 "
        "{%0,%1,%2,%3}, {%4,%5,%6,%7}, {%8,%9}, {%0,%1,%2,%3};"
        : "+f"(c[0]), "+f"(c[1]), "+f"(c[2]), "+f"(c[3])
        : "r"(a0), "r"(a1), "r"(a2), "r"(a3), "r"(b0), "r"(b1));
}

__device__ __forceinline__ uint32_t cvt_hi(float2 v) {
    __nv_bfloat162 h;
    h.x = __float2bfloat16(v.x);
    h.y = __float2bfloat16(v.y);
    return *reinterpret_cast<uint32_t*>(&h);
}
__device__ __forceinline__ uint32_t cvt_lo(float2 v, uint32_t hi) {
    __nv_bfloat162 h = *reinterpret_cast<__nv_bfloat162*>(&hi);
    __nv_bfloat162 l;
    l.x = __float2bfloat16(v.x - __bfloat162float(h.x));
    l.y = __float2bfloat16(v.y - __bfloat162float(h.y));
    return *reinterpret_cast<uint32_t*>(&l);
}

__global__ __launch_bounds__(128, 3)
void multidense_kernel(const float* __restrict__ x_in,
                       const int* __restrict__ inds,
                       const float* __restrict__ params,
                       float* __restrict__ out)
{
    extern __shared__ char smem[];
    const uint32_t sb = smem_u32(smem);
    float* bias_s = reinterpret_cast<float*>(smem + OFF_BIAS);
    float* xbuf   = reinterpret_cast<float*>(smem);            // [32][XSTRIDE], aliases WHI

    const int i = blockIdx.x;
    const int t = threadIdx.x;            // 0..127
    const int node = inds[i] & NODE_MASK;

    const int wid = t >> 5, lane = t & 31;
    const int j0 = (wid >> 1) * 16;
    const int l0 = (wid & 1) * 64;
    const int g = lane >> 2, tg = lane & 3;

    // ---- phase 0: x fp32 coalesced gmem -> smem bounce buffer ----
    // float4 index idx4 = t + 128*r: row = idx4>>5, col4 = idx4&31.
    // LDG.128 coalesced; STS.128 one row per warp-instr, conflict-free.
    {
        const float4* xg4 = reinterpret_cast<const float4*>(x_in + (size_t)i * (J_DIM * IN_F));
        float4* xb4 = reinterpret_cast<float4*>(xbuf);
        #pragma unroll
        for (int r = 0; r < 8; r++) {
            int idx4 = t + 128 * r;
            int row  = idx4 >> 5;
            int col4 = idx4 & 31;
            xb4[row * (XSTRIDE / 4) + col4] = xg4[idx4];
        }
    }
    __syncthreads();

    // ---- phase 1: read x fragments from smem, convert to hi/lo regs ----
    uint32_t ahi[32], alo[32];            // [row01*16 + m]: m = k-octet
    {
        const float* r0p = xbuf + (j0 + g) * XSTRIDE + 2 * tg;
        const float* r1p = xbuf + (j0 + 8 + g) * XSTRIDE + 2 * tg;
        #pragma unroll
        for (int m = 0; m < 16; m++) {
            float2 u0 = *reinterpret_cast<const float2*>(r0p + 8 * m);
            float2 u1 = *reinterpret_cast<const float2*>(r1p + 8 * m);
            ahi[m]      = cvt_hi(u0);  alo[m]      = cvt_lo(u0, ahi[m]);
            ahi[16 + m] = cvt_hi(u1);  alo[16 + m] = cvt_lo(u1, ahi[16 + m]);
        }
    }
    __syncthreads();                       // x buffer dead; WHI plane may be written

    // ---- phase 2: stage + split W (verbatim R13): batched LDG, STS ----
    {
        const float* pg = params + (size_t)node * W_SRC_FLOATS;
        #pragma unroll
        for (int rb = 0; rb < 8; rb++) {
            float v0[8], v1[8];
            int lv[8], kv[8];
            #pragma unroll
            for (int m = 0; m < 8; m++) {
                int pidx = t + 128 * (rb * 8 + m);       // 0..8191
                lv[m] = pidx >> 6;
                kv[m] = (pidx & 63) * 2;
                const float* s = pg + lv[m] * PROW_SRC + kv[m];
                v0[m] = s[0];
                v1[m] = s[1];
            }
            #pragma unroll
            for (int m = 0; m < 8; m++) {
                float2 v = make_float2(v0[m], v1[m]);
                uint32_t hp = cvt_hi(v);
                uint32_t lp = cvt_lo(v, hp);
                uint32_t o = (uint32_t)(lv[m] * RSTRIDE + kv[m]) * 2;
                *reinterpret_cast<uint32_t*>(smem + OFF_WHI + o) = hp;
                *reinterpret_cast<uint32_t*>(smem + OFF_WLO + o) = lp;
            }
        }
        bias_s[t] = pg[t * PROW_SRC + IN_F];
    }
    __syncthreads();                       // W planes ready

    // ---- phase 3: MMA (verbatim R13) ----
    float c[8][4];
    #pragma unroll
    for (int nt = 0; nt < 8; nt++)
        #pragma unroll
        for (int q = 0; q < 4; q++) c[nt][q] = 0.0f;

    const int brow  = l0 + (lane & 7) + (lane >> 4) * 8;
    const int bkoff = ((lane >> 3) & 1) * 8;
    uint32_t b_hi = sb + OFF_WHI + (uint32_t)(brow * RSTRIDE + bkoff) * 2;
    uint32_t b_lo = sb + OFF_WLO + (uint32_t)(brow * RSTRIDE + bkoff) * 2;
    const uint32_t PSTEP = 16 * RSTRIDE * 2;

    #pragma unroll
    for (int ks = 0; ks < 8; ks++) {
        const uint32_t ko = (uint32_t)ks * 32;
        const uint32_t ah0 = ahi[2 * ks],     ah1 = ahi[16 + 2 * ks];
        const uint32_t ah2 = ahi[2 * ks + 1], ah3 = ahi[16 + 2 * ks + 1];
        const uint32_t al0 = alo[2 * ks],     al1 = alo[16 + 2 * ks];
        const uint32_t al2 = alo[2 * ks + 1], al3 = alo[16 + 2 * ks + 1];

        uint32_t bh[4][4], bl[4][4];
        #pragma unroll
        for (int p = 0; p < 4; p++) {
            ldmx4(bh[p], b_hi + p * PSTEP + ko);
            ldmx4(bl[p], b_lo + p * PSTEP + ko);
        }

        #pragma unroll
        for (int nt = 0; nt < 8; nt++) {
            const int p = nt >> 1;
            const int q = (nt & 1) * 2;
            mma_bf16(c[nt], ah0, ah1, ah2, ah3, bh[p][q], bh[p][q + 1]);   // hi*hi
            mma_bf16(c[nt], ah0, ah1, ah2, ah3, bl[p][q], bl[p][q + 1]);   // hi*lo
            mma_bf16(c[nt], al0, al1, al2, al3, bh[p][q], bh[p][q + 1]);   // lo*hi
        }
    }

    // ---- epilogue (verbatim R13) ----
    float* og = out + (size_t)i * (J_DIM * OUT_F);
    #pragma unroll
    for (int nt = 0; nt < 8; nt++) {
        const int l = l0 + nt * 8 + 2 * tg;
        const float2 b2 = *reinterpret_cast<const float2*>(bias_s + l);
        float2 r0; r0.x = c[nt][0] + b2.x; r0.y = c[nt][1] + b2.y;
        float2 r1; r1.x = c[nt][2] + b2.x; r1.y = c[nt][3] + b2.y;
        *reinterpret_cast<float2*>(og + (j0 + g)     * OUT_F + l) = r0;
        *reinterpret_cast<float2*>(og + (j0 + g + 8) * OUT_F + l) = r1;
    }
}

extern "C" void kernel_launch(void* const* d_in, const int* in_sizes, int n_in,
                              void* d_out, int out_size)
{
    const float* x_in   = (const float*)d_in[0];
    const int*   inds   = (const int*)d_in[1];
    const float* params = (const float*)d_in[2];
    float*       out    = (float*)d_out;

    static bool attr_set = false;
    if (!attr_set) {
        cudaFuncSetAttribute(multidense_kernel,
                             cudaFuncAttributeMaxDynamicSharedMemorySize, SMEM_BYTES);
        attr_set = true;
    }

    multidense_kernel<<<I_DIM, 128, SMEM_BYTES>>>(x_in, inds, params, out);
}

// round 17
// speedup vs baseline: 1.1765x; 1.0110x over previous
#include <cuda_runtime.h>
#include <cuda_bf16.h>
#include <cstdint>

// MultiDense via mma.sync: per i, D[j=32, l=128] = x @ W^T + bias, split-bf16
// 3-pass (AhBh + AhBl + AlBh), fp32 accum. One CTA (128 thr) per i, 3 CTAs/SM.
// R17 = R16 + transposed epilogue: c staged into smem (dead plane region),
// flushed with fully-coalesced row-per-instruction STG.128 (512 -> 128 wf).

#define I_DIM 8192
#define J_DIM 32
#define IN_F  128
#define OUT_F 128
#define NODE_MASK 4095
#define PROW_SRC 129
#define W_SRC_FLOATS (OUT_F * PROW_SRC)     // 16512

#define RSTRIDE 136                          // W bf16 row stride: ldmatrix conflict-free
#define XSTRIDE 132                          // x fp32 bounce stride (2-way max conflicts)
#define OSTRIDE 132                          // output fp32 stage stride
#define OFF_WHI 0                            // 128 x 136 bf16 = 34816 (x/out stage alias here)
#define OFF_WLO 34816
#define OFF_BIAS 69632                       // 128 f32
#define SMEM_BYTES 70144                     // 3 CTAs/SM

__device__ __forceinline__ uint32_t smem_u32(const void* p) {
    uint32_t a;
    asm("{ .reg .u64 t; cvta.to.shared.u64 t, %1; cvt.u32.u64 %0, t; }" : "=r"(a) : "l"(p));
    return a;
}

__device__ __forceinline__ void ldmx4(uint32_t* r, uint32_t addr) {
    asm volatile("ldmatrix.sync.aligned.m8n8.x4.shared.b16 {%0,%1,%2,%3}, [%4];"
                 : "=r"(r[0]), "=r"(r[1]), "=r"(r[2]), "=r"(r[3]) : "r"(addr));
}

__device__ __forceinline__ void mma_bf16(float* c, uint32_t a0, uint32_t a1, uint32_t a2,
                                         uint32_t a3, uint32_t b0, uint32_t b1) {
    asm volatile(
        "mma.sync.aligned.m16n8k16.row.col.f32.bf16.bf16.f32 "
        "{%0,%1,%2,%3}, {%4,%5,%6,%7}, {%8,%9}, {%0,%1,%2,%3};"
        : "+f"(c[0]), "+f"(c[1]), "+f"(c[2]), "+f"(c[3])
        : "r"(a0), "r"(a1), "r"(a2), "r"(a3), "r"(b0), "r"(b1));
}

__device__ __forceinline__ uint32_t cvt_hi(float2 v) {
    __nv_bfloat162 h;
    h.x = __float2bfloat16(v.x);
    h.y = __float2bfloat16(v.y);
    return *reinterpret_cast<uint32_t*>(&h);
}
__device__ __forceinline__ uint32_t cvt_lo(float2 v, uint32_t hi) {
    __nv_bfloat162 h = *reinterpret_cast<__nv_bfloat162*>(&hi);
    __nv_bfloat162 l;
    l.x = __float2bfloat16(v.x - __bfloat162float(h.x));
    l.y = __float2bfloat16(v.y - __bfloat162float(h.y));
    return *reinterpret_cast<uint32_t*>(&l);
}

__global__ __launch_bounds__(128, 3)
void multidense_kernel(const float* __restrict__ x_in,
                       const int* __restrict__ inds,
                       const float* __restrict__ params,
                       float* __restrict__ out)
{
    extern __shared__ char smem[];
    const uint32_t sb = smem_u32(smem);
    float* bias_s = reinterpret_cast<float*>(smem + OFF_BIAS);
    float* xbuf   = reinterpret_cast<float*>(smem);            // [32][XSTRIDE], aliases WHI

    const int i = blockIdx.x;
    const int t = threadIdx.x;            // 0..127
    const int node = inds[i] & NODE_MASK;

    const int wid = t >> 5, lane = t & 31;
    const int j0 = (wid >> 1) * 16;
    const int l0 = (wid & 1) * 64;
    const int g = lane >> 2, tg = lane & 3;

    // ---- phase 0: x fp32 coalesced gmem -> smem bounce buffer ----
    {
        const float4* xg4 = reinterpret_cast<const float4*>(x_in + (size_t)i * (J_DIM * IN_F));
        float4* xb4 = reinterpret_cast<float4*>(xbuf);
        #pragma unroll
        for (int r = 0; r < 8; r++) {
            int idx4 = t + 128 * r;
            int row  = idx4 >> 5;
            int col4 = idx4 & 31;
            xb4[row * (XSTRIDE / 4) + col4] = xg4[idx4];
        }
    }
    __syncthreads();

    // ---- phase 1: read x fragments from smem, convert to hi/lo regs ----
    uint32_t ahi[32], alo[32];            // [row01*16 + m]: m = k-octet
    {
        const float* r0p = xbuf + (j0 + g) * XSTRIDE + 2 * tg;
        const float* r1p = xbuf + (j0 + 8 + g) * XSTRIDE + 2 * tg;
        #pragma unroll
        for (int m = 0; m < 16; m++) {
            float2 u0 = *reinterpret_cast<const float2*>(r0p + 8 * m);
            float2 u1 = *reinterpret_cast<const float2*>(r1p + 8 * m);
            ahi[m]      = cvt_hi(u0);  alo[m]      = cvt_lo(u0, ahi[m]);
            ahi[16 + m] = cvt_hi(u1);  alo[16 + m] = cvt_lo(u1, ahi[16 + m]);
        }
    }
    __syncthreads();                       // x buffer dead; WHI plane may be written

    // ---- phase 2: stage + split W (verbatim R13/R16) ----
    {
        const float* pg = params + (size_t)node * W_SRC_FLOATS;
        #pragma unroll
        for (int rb = 0; rb < 8; rb++) {
            float v0[8], v1[8];
            int lv[8], kv[8];
            #pragma unroll
            for (int m = 0; m < 8; m++) {
                int pidx = t + 128 * (rb * 8 + m);       // 0..8191
                lv[m] = pidx >> 6;
                kv[m] = (pidx & 63) * 2;
                const float* s = pg + lv[m] * PROW_SRC + kv[m];
                v0[m] = s[0];
                v1[m] = s[1];
            }
            #pragma unroll
            for (int m = 0; m < 8; m++) {
                float2 v = make_float2(v0[m], v1[m]);
                uint32_t hp = cvt_hi(v);
                uint32_t lp = cvt_lo(v, hp);
                uint32_t o = (uint32_t)(lv[m] * RSTRIDE + kv[m]) * 2;
                *reinterpret_cast<uint32_t*>(smem + OFF_WHI + o) = hp;
                *reinterpret_cast<uint32_t*>(smem + OFF_WLO + o) = lp;
            }
        }
        bias_s[t] = pg[t * PROW_SRC + IN_F];
    }
    __syncthreads();                       // W planes ready

    // ---- phase 3: MMA (verbatim R13/R16) ----
    float c[8][4];
    #pragma unroll
    for (int nt = 0; nt < 8; nt++)
        #pragma unroll
        for (int q = 0; q < 4; q++) c[nt][q] = 0.0f;

    const int brow  = l0 + (lane & 7) + (lane >> 4) * 8;
    const int bkoff = ((lane >> 3) & 1) * 8;
    uint32_t b_hi = sb + OFF_WHI + (uint32_t)(brow * RSTRIDE + bkoff) * 2;
    uint32_t b_lo = sb + OFF_WLO + (uint32_t)(brow * RSTRIDE + bkoff) * 2;
    const uint32_t PSTEP = 16 * RSTRIDE * 2;

    #pragma unroll
    for (int ks = 0; ks < 8; ks++) {
        const uint32_t ko = (uint32_t)ks * 32;
        const uint32_t ah0 = ahi[2 * ks],     ah1 = ahi[16 + 2 * ks];
        const uint32_t ah2 = ahi[2 * ks + 1], ah3 = ahi[16 + 2 * ks + 1];
        const uint32_t al0 = alo[2 * ks],     al1 = alo[16 + 2 * ks];
        const uint32_t al2 = alo[2 * ks + 1], al3 = alo[16 + 2 * ks + 1];

        uint32_t bh[4][4], bl[4][4];
        #pragma unroll
        for (int p = 0; p < 4; p++) {
            ldmx4(bh[p], b_hi + p * PSTEP + ko);
            ldmx4(bl[p], b_lo + p * PSTEP + ko);
        }

        #pragma unroll
        for (int nt = 0; nt < 8; nt++) {
            const int p = nt >> 1;
            const int q = (nt & 1) * 2;
            mma_bf16(c[nt], ah0, ah1, ah2, ah3, bh[p][q], bh[p][q + 1]);   // hi*hi
            mma_bf16(c[nt], ah0, ah1, ah2, ah3, bl[p][q], bl[p][q + 1]);   // hi*lo
            mma_bf16(c[nt], al0, al1, al2, al3, bh[p][q], bh[p][q + 1]);   // lo*hi
        }
    }

    // ---- epilogue: stage c (+bias) into smem, flush coalesced ----
    __syncthreads();                       // all MMAs done; planes dead
    {
        float* ob = reinterpret_cast<float*>(smem);        // [32][OSTRIDE]
        #pragma unroll
        for (int nt = 0; nt < 8; nt++) {
            const int l = l0 + nt * 8 + 2 * tg;
            const float2 b2 = *reinterpret_cast<const float2*>(bias_s + l);
            float2 r0; r0.x = c[nt][0] + b2.x; r0.y = c[nt][1] + b2.y;
            float2 r1; r1.x = c[nt][2] + b2.x; r1.y = c[nt][3] + b2.y;
            *reinterpret_cast<float2*>(ob + (j0 + g)     * OSTRIDE + l) = r0;
            *reinterpret_cast<float2*>(ob + (j0 + g + 8) * OSTRIDE + l) = r1;
        }
    }
    __syncthreads();                       // staged tile complete
    {
        const float4* ob4 = reinterpret_cast<const float4*>(smem);      // stride 33 float4
        float4* og4 = reinterpret_cast<float4*>(out + (size_t)i * (J_DIM * OUT_F));
        #pragma unroll
        for (int r = 0; r < 8; r++) {
            const int row = wid + 4 * r;            // one full row per warp-instr
            og4[row * 32 + lane] = ob4[row * (OSTRIDE / 4) + lane];
        }
    }
}

extern "C" void kernel_launch(void* const* d_in, const int* in_sizes, int n_in,
                              void* d_out, int out_size)
{
    const float* x_in   = (const float*)d_in[0];
    const int*   inds   = (const int*)d_in[1];
    const float* params = (const float*)d_in[2];
    float*       out    = (float*)d_out;

    static bool attr_set = false;
    if (!attr_set) {
        cudaFuncSetAttribute(multidense_kernel,
                             cudaFuncAttributeMaxDynamicSharedMemorySize, SMEM_BYTES);
        attr_set = true;
    }

    multidense_kernel<<<I_DIM, 128, SMEM_BYTES>>>(x_in, inds, params, out);
}